// round 10
// baseline (speedup 1.0000x reference)
#include <cuda_runtime.h>
#include <cuda_fp16.h>
#include <cstdint>

#define IN_F   4096
#define OUT_F  11008
#define M_TOT  512
#define BM     128
#define BN     256
#define BK     64
#define NCHUNK (IN_F / BK)      // 64
#define NTHREADS 256
#define STAGE_BYTES 49152       // A 16KB + B 32KB
static constexpr int SMEM_BYTES = 2 * STAGE_BYTES;   // 96 KB

// x converted to fp16 once per launch (scratch: __device__ global, no allocs)
__device__ __align__(16) __half g_xh[M_TOT * IN_F];

// ---------------- helpers ----------------
__device__ __forceinline__ uint32_t smem_u32(const void* p) {
    uint32_t a;
    asm("{ .reg .u64 t; cvta.to.shared.u64 t, %1; cvt.u32.u64 %0, t; }" : "=r"(a) : "l"(p));
    return a;
}

#define LDSM4(r0, r1, r2, r3, addr) \
    asm volatile("ldmatrix.sync.aligned.m8n8.x4.shared.b16 {%0,%1,%2,%3}, [%4];" \
        : "=r"(r0), "=r"(r1), "=r"(r2), "=r"(r3) : "r"(addr))

#define MMA16816(c, a, b0, b1) \
    asm volatile("mma.sync.aligned.m16n8k16.row.col.f32.f16.f16.f32 " \
        "{%0,%1,%2,%3}, {%4,%5,%6,%7}, {%8,%9}, {%0,%1,%2,%3};" \
        : "+f"((c)[0]), "+f"((c)[1]), "+f"((c)[2]), "+f"((c)[3]) \
        : "r"((a)[0]), "r"((a)[1]), "r"((a)[2]), "r"((a)[3]), "r"(b0), "r"(b1))

#define CP_ASYNC16(dst, src) \
    asm volatile("cp.async.cg.shared.global [%0], [%1], 16;" :: "r"(dst), "l"(src) : "memory")
#define CP_ASYNC_COMMIT() asm volatile("cp.async.commit_group;" ::: "memory")
#define CP_ASYNC_WAIT0()  asm volatile("cp.async.wait_group 0;" ::: "memory")

__device__ __forceinline__ void sts128(uint32_t addr, uint4 v) {
    asm volatile("st.shared.v4.b32 [%0], {%1, %2, %3, %4};"
        :: "r"(addr), "r"(v.x), "r"(v.y), "r"(v.z), "r"(v.w) : "memory");
}

// dequant two int4-codes (stored as int32) -> packed fp16x2
__device__ __forceinline__ uint32_t packw(uint32_t q0, uint32_t q1, float s, float bz) {
    float f0 = fmaf((float)(int)q0, s, bz);
    float f1 = fmaf((float)(int)q1, s, bz);
    __half2 h = __floats2half2_rn(f0, f1);
    return *reinterpret_cast<uint32_t*>(&h);
}

#define SWZ(o) ((uint32_t)(o) ^ ((((uint32_t)(o)) >> 3) & 0x70))

// ---------------- kernel 1: x fp32 -> fp16 ----------------
__global__ void convert_x_kernel(const float* __restrict__ x) {
    int i = blockIdx.x * blockDim.x + threadIdx.x;
    float4 v = reinterpret_cast<const float4*>(x)[i];
    __half2 a = __floats2half2_rn(v.x, v.y);
    __half2 b = __floats2half2_rn(v.z, v.w);
    uint2 u;
    u.x = *reinterpret_cast<uint32_t*>(&a);
    u.y = *reinterpret_cast<uint32_t*>(&b);
    reinterpret_cast<uint2*>(g_xh)[i] = u;
}

// ---------------- kernel 2: dequant + HMMA GEMM ----------------
// Stage layout (per stage, 48KB):
//   A: 128 rows x 64 fp16 (128B/row, SW128)  at +0      (16 KB)
//   B: 256 rows x 64 fp16 (128B/row, SW128)  at +16384  (32 KB)
__global__ __launch_bounds__(NTHREADS, 1)
void qlin_main_kernel(const int* __restrict__ qw,
                      const float* __restrict__ wsc,
                      const float* __restrict__ wzp,
                      const float* __restrict__ bias,
                      float* __restrict__ out) {
    extern __shared__ __align__(1024) char smem[];
    const uint32_t sb = smem_u32(smem);
    const int tid  = threadIdx.x;
    const int lane = tid & 31;
    const int wid  = tid >> 5;
    const int mwarp = wid >> 2;       // 2 M-warps (64 rows each)
    const int nwarp = wid & 3;        // 4 N-warps (64 cols each)
    const int m0 = blockIdx.x * BM;   // 4 M-tiles (fast dim -> weight L2 reuse)
    const int n0 = blockIdx.y * BN;   // 43 N-tiles

    // ---- ldmatrix lane constants (SW128: addr = base ^ (ks<<5)) ----
    const int rA = lane & 15;
    const int cA = lane >> 4;
    const int rB = (lane & 7) | (((lane >> 4) & 1) << 3);
    const int cB = (lane >> 3) & 1;
    uint32_t baseA[4], baseB[4];
    #pragma unroll
    for (int i = 0; i < 4; ++i) {
        const int row = mwarp * 64 + i * 16 + rA;
        baseA[i] = (uint32_t)(row * 128 + ((cA << 4) ^ ((row & 7) << 4)));
    }
    #pragma unroll
    for (int jj = 0; jj < 4; ++jj) {
        const int row = nwarp * 64 + jj * 16 + rB;
        baseB[jj] = (uint32_t)(16384 + row * 128 + ((cB << 4) ^ ((row & 7) << 4)));
    }

    // ---- A loader constants (4 cp.async x 16B per thread) ----
    const int wrowA  = tid >> 3;      // 0..31
    const int kpartA = tid & 7;
    uint32_t dstA[4];
    #pragma unroll
    for (int t = 0; t < 4; ++t) {
        const int row = wrowA + t * 32;
        dstA[t] = (uint32_t)(row * 128) + (uint32_t)((kpartA << 4) ^ ((row & 7) << 4));
    }

    // ---- B loader constants: 4 threads/row, 16 codes each; 64 rows/quarter ----
    const int rowq = tid >> 2;        // 0..63
    const int kp   = tid & 3;

    float acc[4][8][4];
    #pragma unroll
    for (int i = 0; i < 4; ++i)
        #pragma unroll
        for (int j = 0; j < 8; ++j)
            #pragma unroll
            for (int c = 0; c < 4; ++c) acc[i][j][c] = 0.f;

    uint4 q[4];          // 16 staging regs (one quarter)
    float s_, bz_;
    uint32_t sts0_, sts1_;

    auto loadB_q = [&](int kc, int Q) {
        const int row = Q * 64 + rowq;
        const int rowB = n0 + row;
        const int* p = qw + (size_t)rowB * IN_F + kc * BK + kp * 16;
        q[0] = *reinterpret_cast<const uint4*>(p);
        q[1] = *reinterpret_cast<const uint4*>(p + 4);
        q[2] = *reinterpret_cast<const uint4*>(p + 8);
        q[3] = *reinterpret_cast<const uint4*>(p + 12);
        const int g = kc >> 1;
        const float s = wsc[rowB * 32 + g];
        s_  = s;
        bz_ = -wzp[rowB * 32 + g] * s;
        const uint32_t rbase = 16384u + (uint32_t)(row * 128);
        const uint32_t xorv  = (uint32_t)((row & 7) << 4);
        sts0_ = rbase + (((uint32_t)(kp * 32)) ^ xorv);
        sts1_ = rbase + (((uint32_t)(kp * 32 + 16)) ^ xorv);
    };

    auto convertB_q = [&](uint32_t stage) {
        uint4 h0, h1;
        h0.x = packw(q[0].x, q[0].y, s_, bz_);  h0.y = packw(q[0].z, q[0].w, s_, bz_);
        h0.z = packw(q[1].x, q[1].y, s_, bz_);  h0.w = packw(q[1].z, q[1].w, s_, bz_);
        h1.x = packw(q[2].x, q[2].y, s_, bz_);  h1.y = packw(q[2].z, q[2].w, s_, bz_);
        h1.z = packw(q[3].x, q[3].y, s_, bz_);  h1.w = packw(q[3].z, q[3].w, s_, bz_);
        sts128(stage + sts0_, h0);
        sts128(stage + sts1_, h1);
    };

    auto cpasyncA = [&](int kc, uint32_t stage) {
        #pragma unroll
        for (int t = 0; t < 4; ++t) {
            const int row = wrowA + t * 32;
            const __half* src = g_xh + (size_t)(m0 + row) * IN_F + kc * BK + kpartA * 8;
            CP_ASYNC16(stage + dstA[t], src);
        }
        CP_ASYNC_COMMIT();
    };

    auto mmaStep = [&](uint32_t stage, int ks) {
        const uint32_t ax = (uint32_t)(ks << 5);
        uint32_t a[4][4];
        #pragma unroll
        for (int i = 0; i < 4; ++i)
            LDSM4(a[i][0], a[i][1], a[i][2], a[i][3], (stage + baseA[i]) ^ ax);
        uint32_t bf[8][2];
        #pragma unroll
        for (int jj = 0; jj < 4; ++jj) {
            uint32_t r0, r1, r2, r3;
            LDSM4(r0, r1, r2, r3, (stage + baseB[jj]) ^ ax);
            bf[2 * jj][0] = r0;      bf[2 * jj][1] = r1;
            bf[2 * jj + 1][0] = r2;  bf[2 * jj + 1][1] = r3;
        }
        #pragma unroll
        for (int i = 0; i < 4; ++i)
            #pragma unroll
            for (int j = 0; j < 8; ++j)
                MMA16816(acc[i][j], a[i], bf[j][0], bf[j][1]);
    };

    // ---- prologue: chunk 0 into stage 0 ----
    cpasyncA(0, sb);
    #pragma unroll
    for (int Q = 0; Q < 4; ++Q) { loadB_q(0, Q); convertB_q(sb); }
    CP_ASYNC_WAIT0();
    __syncthreads();

    // ---- main loop: double-buffered; B quarters interleaved with ks-steps ----
    for (int kc = 0; kc < NCHUNK; ++kc) {
        const uint32_t cur = sb + (uint32_t)((kc & 1) ? STAGE_BYTES : 0);
        const uint32_t nxt = sb + (uint32_t)((kc & 1) ? 0 : STAGE_BYTES);
        const bool more = (kc + 1 < NCHUNK);
        if (more) { cpasyncA(kc + 1, nxt); loadB_q(kc + 1, 0); }
        mmaStep(cur, 0);
        if (more) { convertB_q(nxt); loadB_q(kc + 1, 1); }
        mmaStep(cur, 1);
        if (more) { convertB_q(nxt); loadB_q(kc + 1, 2); }
        mmaStep(cur, 2);
        if (more) { convertB_q(nxt); loadB_q(kc + 1, 3); }
        mmaStep(cur, 3);
        if (more) { convertB_q(nxt); CP_ASYNC_WAIT0(); }
        __syncthreads();
    }

    // ---- epilogue: direct float2 stores + bias ----
    const int r_base = m0 + mwarp * 64 + (lane >> 2);
    #pragma unroll
    for (int j = 0; j < 8; ++j) {
        const int col = n0 + nwarp * 64 + j * 8 + (lane & 3) * 2;
        const float2 bv = *reinterpret_cast<const float2*>(&bias[col]);
        #pragma unroll
        for (int i = 0; i < 4; ++i) {
            const int r0 = r_base + i * 16;
            float2 v0 = make_float2(acc[i][j][0] + bv.x, acc[i][j][1] + bv.y);
            float2 v1 = make_float2(acc[i][j][2] + bv.x, acc[i][j][3] + bv.y);
            *reinterpret_cast<float2*>(&out[(size_t)r0 * OUT_F + col]) = v0;
            *reinterpret_cast<float2*>(&out[(size_t)(r0 + 8) * OUT_F + col]) = v1;
        }
    }
}

// ---------------- launch ----------------
extern "C" void kernel_launch(void* const* d_in, const int* in_sizes, int n_in,
                              void* d_out, int out_size) {
    (void)in_sizes; (void)n_in; (void)out_size;
    const float* x    = (const float*)d_in[0];
    const int*   qw   = (const int*)d_in[1];
    const float* wsc  = (const float*)d_in[2];
    const float* wzp  = (const float*)d_in[3];
    const float* bias = (const float*)d_in[4];
    float* out = (float*)d_out;

    cudaFuncSetAttribute(qlin_main_kernel,
                         cudaFuncAttributeMaxDynamicSharedMemorySize, SMEM_BYTES);

    convert_x_kernel<<<2048, 256>>>(x);
    qlin_main_kernel<<<dim3(4, 43), NTHREADS, SMEM_BYTES>>>(qw, wsc, wzp, bias, out);
}

// round 11
// speedup vs baseline: 1.0990x; 1.0990x over previous
#include <cuda_runtime.h>
#include <cuda_fp16.h>
#include <cstdint>

#define IN_F   4096
#define OUT_F  11008
#define M_TOT  512
#define BM     128
#define BN     128
#define BK     64
#define NCHUNK (IN_F / BK)      // 64
#define NTHREADS 256

// Stage: A fp16 16KB at +0, B codes 32KB at +16384. 4 stages + 2 B-fp16 bufs.
#define STAGE_SZ   49152
#define CODES_OFF  16384
#define NSTAGES    4
#define BF16_OFF   (NSTAGES * STAGE_SZ)          // 196608
static constexpr int SMEM_BYTES = BF16_OFF + 2 * 16384;   // 229376 (224 KB)

// x converted to fp16 once per launch (scratch: __device__ global, no allocs)
__device__ __align__(16) __half g_xh[M_TOT * IN_F];

// ---------------- helpers ----------------
__device__ __forceinline__ uint32_t smem_u32(const void* p) {
    uint32_t a;
    asm("{ .reg .u64 t; cvta.to.shared.u64 t, %1; cvt.u32.u64 %0, t; }" : "=r"(a) : "l"(p));
    return a;
}

#define LDSM4(r0, r1, r2, r3, addr) \
    asm volatile("ldmatrix.sync.aligned.m8n8.x4.shared.b16 {%0,%1,%2,%3}, [%4];" \
        : "=r"(r0), "=r"(r1), "=r"(r2), "=r"(r3) : "r"(addr))

#define MMA16816(c, a, b0, b1) \
    asm volatile("mma.sync.aligned.m16n8k16.row.col.f32.f16.f16.f32 " \
        "{%0,%1,%2,%3}, {%4,%5,%6,%7}, {%8,%9}, {%0,%1,%2,%3};" \
        : "+f"((c)[0]), "+f"((c)[1]), "+f"((c)[2]), "+f"((c)[3]) \
        : "r"((a)[0]), "r"((a)[1]), "r"((a)[2]), "r"((a)[3]), "r"(b0), "r"(b1))

#define CP_ASYNC16(dst, src) \
    asm volatile("cp.async.cg.shared.global [%0], [%1], 16;" :: "r"(dst), "l"(src) : "memory")
#define CP_ASYNC_COMMIT() asm volatile("cp.async.commit_group;" ::: "memory")
#define CP_ASYNC_WAIT2()  asm volatile("cp.async.wait_group 2;" ::: "memory")

__device__ __forceinline__ void sts128(uint32_t addr, uint4 v) {
    asm volatile("st.shared.v4.b32 [%0], {%1, %2, %3, %4};"
        :: "r"(addr), "r"(v.x), "r"(v.y), "r"(v.z), "r"(v.w) : "memory");
}
__device__ __forceinline__ uint4 lds128(uint32_t addr) {
    uint4 v;
    asm volatile("ld.shared.v4.b32 {%0,%1,%2,%3}, [%4];"
        : "=r"(v.x), "=r"(v.y), "=r"(v.z), "=r"(v.w) : "r"(addr));
    return v;
}

// dequant two int4-codes (stored as int32) -> packed fp16x2
__device__ __forceinline__ uint32_t packw(uint32_t q0, uint32_t q1, float s, float bz) {
    float f0 = fmaf((float)(int)q0, s, bz);
    float f1 = fmaf((float)(int)q1, s, bz);
    __half2 h = __floats2half2_rn(f0, f1);
    return *reinterpret_cast<uint32_t*>(&h);
}

// ---------------- kernel 1: x fp32 -> fp16 ----------------
__global__ void convert_x_kernel(const float* __restrict__ x) {
    int i = blockIdx.x * blockDim.x + threadIdx.x;
    float4 v = reinterpret_cast<const float4*>(x)[i];
    __half2 a = __floats2half2_rn(v.x, v.y);
    __half2 b = __floats2half2_rn(v.z, v.w);
    uint2 u;
    u.x = *reinterpret_cast<uint32_t*>(&a);
    u.y = *reinterpret_cast<uint32_t*>(&b);
    reinterpret_cast<uint2*>(g_xh)[i] = u;
}

// ---------------- kernel 2: dequant + HMMA GEMM ----------------
__global__ __launch_bounds__(NTHREADS, 1)
void qlin_main_kernel(const int* __restrict__ qw,
                      const float* __restrict__ wsc,
                      const float* __restrict__ wzp,
                      const float* __restrict__ bias,
                      float* __restrict__ out) {
    extern __shared__ __align__(1024) char smem[];
    const uint32_t sb = smem_u32(smem);
    const int tid  = threadIdx.x;
    const int lane = tid & 31;
    const int wid  = tid >> 5;
    const int mwarp = wid & 3;        // 4 M-warps (32 rows)
    const int nwarp = wid >> 2;       // 2 N-warps (64 cols)
    const int m0 = blockIdx.x * BM;   // 4 M-tiles (fast dim -> weight L2 reuse)
    const int n0 = blockIdx.y * BN;   // 86 N-tiles

    // ---- ldmatrix lane constants (SW128: addr = base ^ (ks<<5)) ----
    const int rA = lane & 15;
    const int cA = lane >> 4;
    const int rB = (lane & 7) | (((lane >> 4) & 1) << 3);
    const int cB = (lane >> 3) & 1;
    uint32_t baseA[2], baseB[4];
    #pragma unroll
    for (int i = 0; i < 2; ++i) {
        const int row = mwarp * 32 + i * 16 + rA;
        baseA[i] = (uint32_t)(row * 128 + ((cA << 4) ^ ((row & 7) << 4)));
    }
    #pragma unroll
    for (int jj = 0; jj < 4; ++jj) {
        const int row = nwarp * 64 + jj * 16 + rB;
        baseB[jj] = (uint32_t)(row * 128 + ((cB << 4) ^ ((row & 7) << 4)));
    }

    // ---- A loader: 4 cp.async x16B per thread ----
    const int wrowA  = tid >> 3;      // 0..31
    const int kpartA = tid & 7;
    uint32_t dstA[4];
    #pragma unroll
    for (int t = 0; t < 4; ++t) {
        const int row = wrowA + t * 32;
        dstA[t] = (uint32_t)(row * 128) + (uint32_t)((kpartA << 4) ^ ((row & 7) << 4));
    }

    // ---- B loader: thread owns row=tid>>1, kp=tid&1 (codes k in [kp*32, +32)) ----
    const int browL = tid >> 1;       // 0..127
    const int kp    = tid & 1;
    const int rowB  = n0 + browL;
    const int* qsrc = qw + (size_t)rowB * IN_F + kp * 32;
    // conflict-free code-stage addressing: 8 x 16B slots, XOR by ((row&3)*2+kp)<<4
    const uint32_t cXor = (uint32_t)((((browL & 3) << 1) | kp) << 4);
    uint32_t cAddr[8];
    #pragma unroll
    for (int j = 0; j < 8; ++j)
        cAddr[j] = CODES_OFF + (uint32_t)(browL * 256 + kp * 128) + (((uint32_t)(j * 16)) ^ cXor);
    // fp16 B STS addresses (SW128, matches LDSM side)
    const uint32_t bXor = (uint32_t)((browL & 7) << 4);
    uint32_t bsts[4];
    #pragma unroll
    for (int i = 0; i < 4; ++i)
        bsts[i] = (uint32_t)(browL * 128) + (((uint32_t)(kp * 64 + i * 16)) ^ bXor);

    float acc[2][8][4];
    #pragma unroll
    for (int i = 0; i < 2; ++i)
        #pragma unroll
        for (int j = 0; j < 8; ++j)
            #pragma unroll
            for (int c = 0; c < 4; ++c) acc[i][j][c] = 0.f;

    float s_, bz_;

    auto loadScales = [&](int g) {
        const float s = wsc[rowB * 32 + g];
        s_  = s;
        bz_ = -wzp[rowB * 32 + g] * s;
    };

    auto issueStage = [&](int kc) {
        const uint32_t st = sb + (uint32_t)((kc & 3) * STAGE_SZ);
        // A tile
        #pragma unroll
        for (int t = 0; t < 4; ++t) {
            const int row = wrowA + t * 32;
            const __half* src = g_xh + (size_t)(m0 + row) * IN_F + kc * BK + kpartA * 8;
            CP_ASYNC16(st + dstA[t], src);
        }
        // B codes (raw int32), each thread copies its own 128B
        const int* p = qsrc + kc * BK;
        #pragma unroll
        for (int j = 0; j < 8; ++j)
            CP_ASYNC16(st + cAddr[j], p + j * 4);
    };

    // convert half h (codes j = 4h..4h+3 -> 2 STS.128) reading own cp.async data
    auto convertHalf = [&](uint32_t stCodes, uint32_t bfW, int h) {
        uint4 c0 = lds128(stCodes + cAddr[4 * h + 0]);
        uint4 c1 = lds128(stCodes + cAddr[4 * h + 1]);
        uint4 c2 = lds128(stCodes + cAddr[4 * h + 2]);
        uint4 c3 = lds128(stCodes + cAddr[4 * h + 3]);
        uint4 h0, h1;
        h0.x = packw(c0.x, c0.y, s_, bz_);  h0.y = packw(c0.z, c0.w, s_, bz_);
        h0.z = packw(c1.x, c1.y, s_, bz_);  h0.w = packw(c1.z, c1.w, s_, bz_);
        h1.x = packw(c2.x, c2.y, s_, bz_);  h1.y = packw(c2.z, c2.w, s_, bz_);
        h1.z = packw(c3.x, c3.y, s_, bz_);  h1.w = packw(c3.z, c3.w, s_, bz_);
        sts128(bfW + bsts[2 * h + 0], h0);
        sts128(bfW + bsts[2 * h + 1], h1);
    };

    auto mmaStep = [&](uint32_t stA, uint32_t bfR, int ks) {
        const uint32_t ax = (uint32_t)(ks << 5);
        uint32_t a[2][4];
        LDSM4(a[0][0], a[0][1], a[0][2], a[0][3], (stA + baseA[0]) ^ ax);
        LDSM4(a[1][0], a[1][1], a[1][2], a[1][3], (stA + baseA[1]) ^ ax);
        uint32_t bf[8][2];
        #pragma unroll
        for (int jj = 0; jj < 4; ++jj) {
            uint32_t r0, r1, r2, r3;
            LDSM4(r0, r1, r2, r3, (bfR + baseB[jj]) ^ ax);
            bf[2 * jj][0] = r0;      bf[2 * jj][1] = r1;
            bf[2 * jj + 1][0] = r2;  bf[2 * jj + 1][1] = r3;
        }
        #pragma unroll
        for (int i = 0; i < 2; ++i)
            #pragma unroll
            for (int j = 0; j < 8; ++j)
                MMA16816(acc[i][j], a[i], bf[j][0], bf[j][1]);
    };

    // ---- prologue: chunks 0,1,2 in flight; convert chunk 0 ----
    issueStage(0); CP_ASYNC_COMMIT();
    issueStage(1); CP_ASYNC_COMMIT();
    issueStage(2); CP_ASYNC_COMMIT();
    loadScales(0);
    CP_ASYNC_WAIT2();                           // group 0 complete (own data)
    {
        const uint32_t stC = sb;                // stage 0 codes
        const uint32_t bf0 = sb + BF16_OFF;     // buffer 0
        convertHalf(stC, bf0, 0);
        convertHalf(stC, bf0, 1);
    }
    __syncthreads();                            // publish A(0) + Bf16(0)

    // ---- main loop ----
    for (int kc = 0; kc < NCHUNK; ++kc) {
        const uint32_t stA = sb + (uint32_t)((kc & 3) * STAGE_SZ);
        const uint32_t stC = sb + (uint32_t)(((kc + 1) & 3) * STAGE_SZ);
        const uint32_t bfR = sb + BF16_OFF + (uint32_t)((kc & 1) << 14);
        const uint32_t bfW = sb + BF16_OFF + (uint32_t)(((kc + 1) & 1) << 14);
        const bool more = (kc + 1 < NCHUNK);

        if (kc + 3 < NCHUNK) issueStage(kc + 3);
        CP_ASYNC_COMMIT();                      // always: keeps group count aligned
        if (more && (((kc + 1) & 1) == 0)) loadScales((kc + 1) >> 1);

        mmaStep(stA, bfR, 0);
        mmaStep(stA, bfR, 1);
        if (more) {
            CP_ASYNC_WAIT2();                   // stage(kc+1) input complete
            convertHalf(stC, bfW, 0);
        }
        mmaStep(stA, bfR, 2);
        if (more) convertHalf(stC, bfW, 1);
        mmaStep(stA, bfR, 3);
        __syncthreads();
    }

    // ---- epilogue: direct float2 stores + bias ----
    const int r_base = m0 + mwarp * 32 + (lane >> 2);
    #pragma unroll
    for (int j = 0; j < 8; ++j) {
        const int col = n0 + nwarp * 64 + j * 8 + (lane & 3) * 2;
        const float2 bv = *reinterpret_cast<const float2*>(&bias[col]);
        #pragma unroll
        for (int i = 0; i < 2; ++i) {
            const int r0 = r_base + i * 16;
            float2 v0 = make_float2(acc[i][j][0] + bv.x, acc[i][j][1] + bv.y);
            float2 v1 = make_float2(acc[i][j][2] + bv.x, acc[i][j][3] + bv.y);
            *reinterpret_cast<float2*>(&out[(size_t)r0 * OUT_F + col]) = v0;
            *reinterpret_cast<float2*>(&out[(size_t)(r0 + 8) * OUT_F + col]) = v1;
        }
    }
}

// ---------------- launch ----------------
extern "C" void kernel_launch(void* const* d_in, const int* in_sizes, int n_in,
                              void* d_out, int out_size) {
    (void)in_sizes; (void)n_in; (void)out_size;
    const float* x    = (const float*)d_in[0];
    const int*   qw   = (const int*)d_in[1];
    const float* wsc  = (const float*)d_in[2];
    const float* wzp  = (const float*)d_in[3];
    const float* bias = (const float*)d_in[4];
    float* out = (float*)d_out;

    cudaFuncSetAttribute(qlin_main_kernel,
                         cudaFuncAttributeMaxDynamicSharedMemorySize, SMEM_BYTES);

    convert_x_kernel<<<2048, 256>>>(x);
    qlin_main_kernel<<<dim3(4, 86), NTHREADS, SMEM_BYTES>>>(qw, wsc, wzp, bias, out);
}

// round 12
// speedup vs baseline: 1.1347x; 1.0324x over previous
#include <cuda_runtime.h>
#include <cuda_fp16.h>
#include <cstdint>

#define IN_F   4096
#define OUT_F  11008
#define M_TOT  512
#define BM     64
#define BN     128
#define BK     64
#define NCHUNK (IN_F / BK)      // 64
#define NTHREADS 128
#define STAGE_SZ 24576          // A 8KB + B 16KB
static constexpr int SMEM_BYTES = 2 * STAGE_SZ;   // 48 KB (x2 CTAs = 96 KB/SM)

// x converted to fp16 once per launch (scratch: __device__ global, no allocs)
__device__ __align__(16) __half g_xh[M_TOT * IN_F];

// ---------------- helpers ----------------
__device__ __forceinline__ uint32_t smem_u32(const void* p) {
    uint32_t a;
    asm("{ .reg .u64 t; cvta.to.shared.u64 t, %1; cvt.u32.u64 %0, t; }" : "=r"(a) : "l"(p));
    return a;
}

#define LDSM4(r0, r1, r2, r3, addr) \
    asm volatile("ldmatrix.sync.aligned.m8n8.x4.shared.b16 {%0,%1,%2,%3}, [%4];" \
        : "=r"(r0), "=r"(r1), "=r"(r2), "=r"(r3) : "r"(addr))

#define MMA16816(c, a, b0, b1) \
    asm volatile("mma.sync.aligned.m16n8k16.row.col.f32.f16.f16.f32 " \
        "{%0,%1,%2,%3}, {%4,%5,%6,%7}, {%8,%9}, {%0,%1,%2,%3};" \
        : "+f"((c)[0]), "+f"((c)[1]), "+f"((c)[2]), "+f"((c)[3]) \
        : "r"((a)[0]), "r"((a)[1]), "r"((a)[2]), "r"((a)[3]), "r"(b0), "r"(b1))

#define CP_ASYNC16(dst, src) \
    asm volatile("cp.async.cg.shared.global [%0], [%1], 16;" :: "r"(dst), "l"(src) : "memory")
#define CP_ASYNC_COMMIT() asm volatile("cp.async.commit_group;" ::: "memory")
#define CP_ASYNC_WAIT0()  asm volatile("cp.async.wait_group 0;" ::: "memory")

__device__ __forceinline__ void sts128(uint32_t addr, uint4 v) {
    asm volatile("st.shared.v4.b32 [%0], {%1, %2, %3, %4};"
        :: "r"(addr), "r"(v.x), "r"(v.y), "r"(v.z), "r"(v.w) : "memory");
}

// dequant two int4-codes (stored as int32) -> packed fp16x2
__device__ __forceinline__ uint32_t packw(uint32_t q0, uint32_t q1, float s, float bz) {
    float f0 = fmaf((float)(int)q0, s, bz);
    float f1 = fmaf((float)(int)q1, s, bz);
    __half2 h = __floats2half2_rn(f0, f1);
    return *reinterpret_cast<uint32_t*>(&h);
}

// ---------------- kernel 1: x fp32 -> fp16 ----------------
__global__ void convert_x_kernel(const float* __restrict__ x) {
    int i = blockIdx.x * blockDim.x + threadIdx.x;
    float4 v = reinterpret_cast<const float4*>(x)[i];
    __half2 a = __floats2half2_rn(v.x, v.y);
    __half2 b = __floats2half2_rn(v.z, v.w);
    uint2 u;
    u.x = *reinterpret_cast<uint32_t*>(&a);
    u.y = *reinterpret_cast<uint32_t*>(&b);
    reinterpret_cast<uint2*>(g_xh)[i] = u;
}

// ---------------- kernel 2: dequant + HMMA GEMM ----------------
// Stage layout (per stage, 24KB):
//   A:  64 rows x 64 fp16 (128B/row, SW128) at +0     (8 KB)
//   B: 128 rows x 64 fp16 (128B/row, SW128) at +8192  (16 KB)
__global__ __launch_bounds__(NTHREADS, 2)
void qlin_main_kernel(const int* __restrict__ qw,
                      const float* __restrict__ wsc,
                      const float* __restrict__ wzp,
                      const float* __restrict__ bias,
                      float* __restrict__ out) {
    extern __shared__ __align__(1024) char smem[];
    const uint32_t sb = smem_u32(smem);
    const int tid  = threadIdx.x;
    const int lane = tid & 31;
    const int wid  = tid >> 5;        // 4 warps
    const int mwarp = wid & 1;        // 2 M-warps (32 rows each)
    const int nwarp = wid >> 1;       // 2 N-warps (64 cols each)
    const int m0 = blockIdx.x * BM;   // 8 M-tiles (fast dim -> weight L2 reuse)
    const int n0 = blockIdx.y * BN;   // 86 N-tiles

    // ---- ldmatrix lane constants (SW128: addr = base ^ (ks<<5)) ----
    const int rA = lane & 15;
    const int cA = lane >> 4;
    const int rB = (lane & 7) | (((lane >> 4) & 1) << 3);
    const int cB = (lane >> 3) & 1;
    uint32_t baseA[2], baseB[4];
    #pragma unroll
    for (int i = 0; i < 2; ++i) {
        const int row = mwarp * 32 + i * 16 + rA;
        baseA[i] = (uint32_t)(row * 128 + ((cA << 4) ^ ((row & 7) << 4)));
    }
    #pragma unroll
    for (int jj = 0; jj < 4; ++jj) {
        const int row = nwarp * 64 + jj * 16 + rB;
        baseB[jj] = (uint32_t)(8192 + row * 128 + ((cB << 4) ^ ((row & 7) << 4)));
    }

    // ---- A loader: 4 cp.async x16B per thread (8KB total) ----
    const int wrowA  = tid >> 3;      // 0..15
    const int kpartA = tid & 7;
    uint32_t dstA[4];
    #pragma unroll
    for (int t = 0; t < 4; ++t) {
        const int row = wrowA + t * 16;
        dstA[t] = (uint32_t)(row * 128) + (uint32_t)((kpartA << 4) ^ ((row & 7) << 4));
    }

    // ---- B loader: 4 threads/row (16 codes each), rows wrowB + t*32 ----
    const int wrowB = tid >> 2;       // 0..31
    const int kpart = tid & 3;
    uint32_t dstB[4][2];
    #pragma unroll
    for (int t = 0; t < 4; ++t) {
        const int row = wrowB + t * 32;
        const uint32_t xorv = (uint32_t)((row & 7) << 4);
        dstB[t][0] = 8192u + (uint32_t)(row * 128) + (((uint32_t)(kpart * 32)) ^ xorv);
        dstB[t][1] = 8192u + (uint32_t)(row * 128) + (((uint32_t)(kpart * 32 + 16)) ^ xorv);
    }

    float acc[2][8][4];
    #pragma unroll
    for (int i = 0; i < 2; ++i)
        #pragma unroll
        for (int j = 0; j < 8; ++j)
            #pragma unroll
            for (int c = 0; c < 4; ++c) acc[i][j][c] = 0.f;

    uint4 q[2][4];            // staging for one half (2 rows x 16 codes) = 32 regs
    float s_[4], bz_[4];      // per-t scales (persist across a kc pair)

    // B weight LDG (int32 codes) for half h (t = 2h, 2h+1)
    auto loadB_h = [&](int kc, int h) {
        #pragma unroll
        for (int t = 0; t < 2; ++t) {
            const int tt = 2 * h + t;
            const int row = n0 + wrowB + tt * 32;
            const int* p = qw + (size_t)row * IN_F + kc * BK + kpart * 16;
            q[t][0] = *reinterpret_cast<const uint4*>(p);
            q[t][1] = *reinterpret_cast<const uint4*>(p + 4);
            q[t][2] = *reinterpret_cast<const uint4*>(p + 8);
            q[t][3] = *reinterpret_cast<const uint4*>(p + 12);
            if ((kc & 1) == 0) {
                const int g = kc >> 1;
                const float s = wsc[row * 32 + g];
                s_[tt] = s;
                bz_[tt] = -wzp[row * 32 + g] * s;
            }
        }
    };

    auto convertB_h = [&](uint32_t stage, int h) {
        #pragma unroll
        for (int t = 0; t < 2; ++t) {
            const int tt = 2 * h + t;
            uint4 h0, h1;
            h0.x = packw(q[t][0].x, q[t][0].y, s_[tt], bz_[tt]);
            h0.y = packw(q[t][0].z, q[t][0].w, s_[tt], bz_[tt]);
            h0.z = packw(q[t][1].x, q[t][1].y, s_[tt], bz_[tt]);
            h0.w = packw(q[t][1].z, q[t][1].w, s_[tt], bz_[tt]);
            h1.x = packw(q[t][2].x, q[t][2].y, s_[tt], bz_[tt]);
            h1.y = packw(q[t][2].z, q[t][2].w, s_[tt], bz_[tt]);
            h1.z = packw(q[t][3].x, q[t][3].y, s_[tt], bz_[tt]);
            h1.w = packw(q[t][3].z, q[t][3].w, s_[tt], bz_[tt]);
            sts128(stage + dstB[tt][0], h0);
            sts128(stage + dstB[tt][1], h1);
        }
    };

    auto cpasyncA = [&](int kc, uint32_t stage) {
        #pragma unroll
        for (int t = 0; t < 4; ++t) {
            const int row = wrowA + t * 16;
            const __half* src = g_xh + (size_t)(m0 + row) * IN_F + kc * BK + kpartA * 8;
            CP_ASYNC16(stage + dstA[t], src);
        }
        CP_ASYNC_COMMIT();
    };

    // two ks-steps of MMA (ks = k0, k0+1)
    auto mmaSteps = [&](uint32_t stage, int k0) {
        #pragma unroll
        for (int ks = k0; ks < k0 + 2; ++ks) {
            const uint32_t ax = (uint32_t)(ks << 5);
            uint32_t a[2][4];
            LDSM4(a[0][0], a[0][1], a[0][2], a[0][3], (stage + baseA[0]) ^ ax);
            LDSM4(a[1][0], a[1][1], a[1][2], a[1][3], (stage + baseA[1]) ^ ax);
            uint32_t bf[8][2];
            #pragma unroll
            for (int jj = 0; jj < 4; ++jj) {
                uint32_t r0, r1, r2, r3;
                LDSM4(r0, r1, r2, r3, (stage + baseB[jj]) ^ ax);
                bf[2 * jj][0] = r0;      bf[2 * jj][1] = r1;
                bf[2 * jj + 1][0] = r2;  bf[2 * jj + 1][1] = r3;
            }
            #pragma unroll
            for (int i = 0; i < 2; ++i)
                #pragma unroll
                for (int j = 0; j < 8; ++j)
                    MMA16816(acc[i][j], a[i], bf[j][0], bf[j][1]);
        }
    };

    // ---- prologue: chunk 0 into stage 0 ----
    loadB_h(0, 0);
    cpasyncA(0, sb);
    convertB_h(sb, 0);
    loadB_h(0, 1);
    convertB_h(sb, 1);
    CP_ASYNC_WAIT0();
    __syncthreads();

    // ---- main loop (double buffered; B load/convert split around MMA halves) ----
    for (int kc = 0; kc < NCHUNK; ++kc) {
        const uint32_t cur = sb + (uint32_t)((kc & 1) ? STAGE_SZ : 0);
        const uint32_t nxt = sb + (uint32_t)((kc & 1) ? 0 : STAGE_SZ);
        const bool more = (kc + 1 < NCHUNK);
        if (more) {
            loadB_h(kc + 1, 0);
            cpasyncA(kc + 1, nxt);
        }
        mmaSteps(cur, 0);
        if (more) {
            convertB_h(nxt, 0);
            loadB_h(kc + 1, 1);
        }
        mmaSteps(cur, 2);
        if (more) {
            convertB_h(nxt, 1);
            CP_ASYNC_WAIT0();
        }
        __syncthreads();
    }

    // ---- epilogue: direct float2 stores + bias ----
    const int r_base = m0 + mwarp * 32 + (lane >> 2);
    #pragma unroll
    for (int j = 0; j < 8; ++j) {
        const int col = n0 + nwarp * 64 + j * 8 + (lane & 3) * 2;
        const float2 bv = *reinterpret_cast<const float2*>(&bias[col]);
        #pragma unroll
        for (int i = 0; i < 2; ++i) {
            const int r0 = r_base + i * 16;
            float2 v0 = make_float2(acc[i][j][0] + bv.x, acc[i][j][1] + bv.y);
            float2 v1 = make_float2(acc[i][j][2] + bv.x, acc[i][j][3] + bv.y);
            *reinterpret_cast<float2*>(&out[(size_t)r0 * OUT_F + col]) = v0;
            *reinterpret_cast<float2*>(&out[(size_t)(r0 + 8) * OUT_F + col]) = v1;
        }
    }
}

// ---------------- launch ----------------
extern "C" void kernel_launch(void* const* d_in, const int* in_sizes, int n_in,
                              void* d_out, int out_size) {
    (void)in_sizes; (void)n_in; (void)out_size;
    const float* x    = (const float*)d_in[0];
    const int*   qw   = (const int*)d_in[1];
    const float* wsc  = (const float*)d_in[2];
    const float* wzp  = (const float*)d_in[3];
    const float* bias = (const float*)d_in[4];
    float* out = (float*)d_out;

    cudaFuncSetAttribute(qlin_main_kernel,
                         cudaFuncAttributeMaxDynamicSharedMemorySize, SMEM_BYTES);

    convert_x_kernel<<<2048, 256>>>(x);
    qlin_main_kernel<<<dim3(8, 86), NTHREADS, SMEM_BYTES>>>(qw, wsc, wzp, bias, out);
}

// round 13
// speedup vs baseline: 1.4163x; 1.2482x over previous
#include <cuda_runtime.h>
#include <cuda_fp16.h>
#include <cstdint>

#define IN_F   4096
#define OUT_F  11008
#define M_TOT  512
#define BM     256
#define BN     128
#define BK     64
#define KHALF  2048
#define NCHUNK (KHALF / BK)     // 32
#define NTHREADS 256
#define STAGE_SZ 49152          // A 32KB + B 16KB
static constexpr int SMEM_BYTES = 2 * STAGE_SZ;   // 96 KB

// x converted to fp16 once per launch (scratch: __device__ global, no allocs)
__device__ __align__(16) __half g_xh[M_TOT * IN_F];

// ---------------- helpers ----------------
__device__ __forceinline__ uint32_t smem_u32(const void* p) {
    uint32_t a;
    asm("{ .reg .u64 t; cvta.to.shared.u64 t, %1; cvt.u32.u64 %0, t; }" : "=r"(a) : "l"(p));
    return a;
}

#define LDSM4(r0, r1, r2, r3, addr) \
    asm volatile("ldmatrix.sync.aligned.m8n8.x4.shared.b16 {%0,%1,%2,%3}, [%4];" \
        : "=r"(r0), "=r"(r1), "=r"(r2), "=r"(r3) : "r"(addr))

#define MMA16816(c, a, b0, b1) \
    asm volatile("mma.sync.aligned.m16n8k16.row.col.f32.f16.f16.f32 " \
        "{%0,%1,%2,%3}, {%4,%5,%6,%7}, {%8,%9}, {%0,%1,%2,%3};" \
        : "+f"((c)[0]), "+f"((c)[1]), "+f"((c)[2]), "+f"((c)[3]) \
        : "r"((a)[0]), "r"((a)[1]), "r"((a)[2]), "r"((a)[3]), "r"(b0), "r"(b1))

#define CP_ASYNC16(dst, src) \
    asm volatile("cp.async.cg.shared.global [%0], [%1], 16;" :: "r"(dst), "l"(src) : "memory")
#define CP_ASYNC_COMMIT() asm volatile("cp.async.commit_group;" ::: "memory")
#define CP_ASYNC_WAIT0()  asm volatile("cp.async.wait_group 0;" ::: "memory")

__device__ __forceinline__ void sts128(uint32_t addr, uint4 v) {
    asm volatile("st.shared.v4.b32 [%0], {%1, %2, %3, %4};"
        :: "r"(addr), "r"(v.x), "r"(v.y), "r"(v.z), "r"(v.w) : "memory");
}

// dequant two int4-codes (stored as int32) -> packed fp16x2
__device__ __forceinline__ uint32_t packw(uint32_t q0, uint32_t q1, float s, float bz) {
    float f0 = fmaf((float)(int)q0, s, bz);
    float f1 = fmaf((float)(int)q1, s, bz);
    __half2 h = __floats2half2_rn(f0, f1);
    return *reinterpret_cast<uint32_t*>(&h);
}

// ---------------- kernel 1: x fp32 -> fp16 ----------------
__global__ void convert_x_kernel(const float* __restrict__ x) {
    int i = blockIdx.x * blockDim.x + threadIdx.x;
    float4 v = reinterpret_cast<const float4*>(x)[i];
    __half2 a = __floats2half2_rn(v.x, v.y);
    __half2 b = __floats2half2_rn(v.z, v.w);
    uint2 u;
    u.x = *reinterpret_cast<uint32_t*>(&a);
    u.y = *reinterpret_cast<uint32_t*>(&b);
    reinterpret_cast<uint2*>(g_xh)[i] = u;
}

// ---------------- kernel 2: dequant + HMMA GEMM (K-split, atomic combine) ----
// Stage layout (per stage, 48KB):
//   A: 256 rows x 64 fp16 (128B/row, SW128) at +0      (32 KB)
//   B: 128 rows x 64 fp16 (128B/row, SW128) at +32768  (16 KB)
__global__ __launch_bounds__(NTHREADS, 1)
void qlin_main_kernel(const int* __restrict__ qw,
                      const float* __restrict__ wsc,
                      const float* __restrict__ wzp,
                      const float* __restrict__ bias,
                      float* __restrict__ out) {
    extern __shared__ __align__(1024) char smem[];
    const uint32_t sb = smem_u32(smem);
    const int tid  = threadIdx.x;
    const int lane = tid & 31;
    const int wid  = tid >> 5;
    const int mwarp = wid & 3;        // 4 M-warps (64 rows each)
    const int nwarp = wid >> 2;       // 2 N-warps (64 cols each)
    const int m0 = blockIdx.x * BM;   // 2 M-tiles (fast dim -> weight L2 reuse)
    const int n0 = blockIdx.y * BN;   // 86 N-tiles
    const int kh = blockIdx.z;        // 2 K-splits
    const int kbase = kh * KHALF;

    // ---- ldmatrix lane constants (SW128: addr = base ^ (ks<<5)) ----
    const int rA = lane & 15;
    const int cA = lane >> 4;
    const int rB = (lane & 7) | (((lane >> 4) & 1) << 3);
    const int cB = (lane >> 3) & 1;
    uint32_t baseA[4], baseB[4];
    #pragma unroll
    for (int i = 0; i < 4; ++i) {
        const int row = mwarp * 64 + i * 16 + rA;
        baseA[i] = (uint32_t)(row * 128 + ((cA << 4) ^ ((row & 7) << 4)));
    }
    #pragma unroll
    for (int jj = 0; jj < 4; ++jj) {
        const int row = nwarp * 64 + jj * 16 + rB;
        baseB[jj] = (uint32_t)(32768 + row * 128 + ((cB << 4) ^ ((row & 7) << 4)));
    }

    // ---- A loader: 8 cp.async x16B per thread (32KB/chunk) ----
    uint32_t dstA[8];
    int rowA[8], prtA[8];
    #pragma unroll
    for (int t = 0; t < 8; ++t) {
        const int c = tid + t * NTHREADS;   // 0..2047
        rowA[t] = c >> 3;                   // 0..255
        prtA[t] = c & 7;
        dstA[t] = (uint32_t)(rowA[t] * 128) + (uint32_t)((prtA[t] << 4) ^ ((rowA[t] & 7) << 4));
    }

    // ---- B loader (identical to R6): 8 threads/row, rows wrow + t*32 ----
    const int wrow  = tid >> 3;       // 0..31
    const int kpart = tid & 7;
    uint32_t dstB[4];
    #pragma unroll
    for (int t = 0; t < 4; ++t) {
        const int row = wrow + t * 32;
        dstB[t] = 32768u + (uint32_t)(row * 128) + (uint32_t)((kpart << 4) ^ ((row & 7) << 4));
    }

    float acc[4][8][4];
    #pragma unroll
    for (int i = 0; i < 4; ++i)
        #pragma unroll
        for (int j = 0; j < 8; ++j)
            #pragma unroll
            for (int c = 0; c < 4; ++c) acc[i][j][c] = 0.f;

    uint4 qa[2], qb[2];       // 16 staging regs (one half = rows t, t+1)
    float s_[4], bz_[4];      // per-t scales (persist across a kc pair)

    // B weight LDG (int32 codes) for half h (t = 2h, 2h+1)
    auto loadB_h = [&](int kc, int h) {
        #pragma unroll
        for (int t = 0; t < 2; ++t) {
            const int tt = 2 * h + t;
            const int row = n0 + wrow + tt * 32;
            const int* p = qw + (size_t)row * IN_F + kbase + kc * BK + kpart * 8;
            qa[t] = *reinterpret_cast<const uint4*>(p);
            qb[t] = *reinterpret_cast<const uint4*>(p + 4);
            if ((kc & 1) == 0) {
                const int g = kh * 16 + (kc >> 1);
                const float s = wsc[row * 32 + g];
                s_[tt] = s;
                bz_[tt] = -wzp[row * 32 + g] * s;
            }
        }
    };

    auto convertB_h = [&](uint32_t stage, int h) {
        #pragma unroll
        for (int t = 0; t < 2; ++t) {
            const int tt = 2 * h + t;
            uint4 hh;
            hh.x = packw(qa[t].x, qa[t].y, s_[tt], bz_[tt]);
            hh.y = packw(qa[t].z, qa[t].w, s_[tt], bz_[tt]);
            hh.z = packw(qb[t].x, qb[t].y, s_[tt], bz_[tt]);
            hh.w = packw(qb[t].z, qb[t].w, s_[tt], bz_[tt]);
            sts128(stage + dstB[tt], hh);
        }
    };

    auto cpasyncA = [&](int kc, uint32_t stage) {
        #pragma unroll
        for (int t = 0; t < 8; ++t) {
            const __half* src = g_xh + (size_t)(m0 + rowA[t]) * IN_F + kbase + kc * BK + prtA[t] * 8;
            CP_ASYNC16(stage + dstA[t], src);
        }
        CP_ASYNC_COMMIT();
    };

    // two ks-steps of MMA (ks = k0, k0+1)
    auto mmaSteps = [&](uint32_t stage, int k0) {
        #pragma unroll
        for (int ks = k0; ks < k0 + 2; ++ks) {
            const uint32_t ax = (uint32_t)(ks << 5);
            uint32_t a[4][4];
            #pragma unroll
            for (int i = 0; i < 4; ++i)
                LDSM4(a[i][0], a[i][1], a[i][2], a[i][3], (stage + baseA[i]) ^ ax);
            uint32_t bf[8][2];
            #pragma unroll
            for (int jj = 0; jj < 4; ++jj) {
                uint32_t r0, r1, r2, r3;
                LDSM4(r0, r1, r2, r3, (stage + baseB[jj]) ^ ax);
                bf[2 * jj][0] = r0;      bf[2 * jj][1] = r1;
                bf[2 * jj + 1][0] = r2;  bf[2 * jj + 1][1] = r3;
            }
            #pragma unroll
            for (int i = 0; i < 4; ++i)
                #pragma unroll
                for (int j = 0; j < 8; ++j)
                    MMA16816(acc[i][j], a[i], bf[j][0], bf[j][1]);
        }
    };

    // ---- prologue: chunk 0 into stage 0 ----
    loadB_h(0, 0);
    cpasyncA(0, sb);
    convertB_h(sb, 0);
    loadB_h(0, 1);
    convertB_h(sb, 1);
    CP_ASYNC_WAIT0();
    __syncthreads();

    // ---- main loop (double buffered; B load/convert split around MMA halves) ----
    for (int kc = 0; kc < NCHUNK; ++kc) {
        const uint32_t cur = sb + (uint32_t)((kc & 1) ? STAGE_SZ : 0);
        const uint32_t nxt = sb + (uint32_t)((kc & 1) ? 0 : STAGE_SZ);
        const bool more = (kc + 1 < NCHUNK);
        if (more) {
            loadB_h(kc + 1, 0);
            cpasyncA(kc + 1, nxt);
        }
        mmaSteps(cur, 0);
        if (more) {
            convertB_h(nxt, 0);
            loadB_h(kc + 1, 1);
        }
        mmaSteps(cur, 2);
        if (more) {
            convertB_h(nxt, 1);
            CP_ASYNC_WAIT0();
        }
        __syncthreads();
    }

    // ---- epilogue: atomic combine (2 deterministic contributions per element) ----
    const int r_base = m0 + mwarp * 64 + (lane >> 2);
    #pragma unroll
    for (int j = 0; j < 8; ++j) {
        const int col = n0 + nwarp * 64 + j * 8 + (lane & 3) * 2;
        float2 bv = make_float2(0.f, 0.f);
        if (kh == 0) bv = *reinterpret_cast<const float2*>(&bias[col]);
        #pragma unroll
        for (int i = 0; i < 4; ++i) {
            const int r0 = r_base + i * 16;
            float* p0 = &out[(size_t)r0 * OUT_F + col];
            float* p1 = &out[(size_t)(r0 + 8) * OUT_F + col];
            atomicAdd(p0,     acc[i][j][0] + bv.x);
            atomicAdd(p0 + 1, acc[i][j][1] + bv.y);
            atomicAdd(p1,     acc[i][j][2] + bv.x);
            atomicAdd(p1 + 1, acc[i][j][3] + bv.y);
        }
    }
}

// ---------------- launch ----------------
extern "C" void kernel_launch(void* const* d_in, const int* in_sizes, int n_in,
                              void* d_out, int out_size) {
    (void)in_sizes; (void)n_in;
    const float* x    = (const float*)d_in[0];
    const int*   qw   = (const int*)d_in[1];
    const float* wsc  = (const float*)d_in[2];
    const float* wzp  = (const float*)d_in[3];
    const float* bias = (const float*)d_in[4];
    float* out = (float*)d_out;

    cudaFuncSetAttribute(qlin_main_kernel,
                         cudaFuncAttributeMaxDynamicSharedMemorySize, SMEM_BYTES);

    cudaMemsetAsync(out, 0, (size_t)out_size * sizeof(float));
    convert_x_kernel<<<2048, 256>>>(x);
    qlin_main_kernel<<<dim3(2, 86, 2), NTHREADS, SMEM_BYTES>>>(qw, wsc, wzp, bias, out);
}

// round 15
// speedup vs baseline: 2.2100x; 1.5604x over previous
#include <cuda_runtime.h>
#include <cuda_fp16.h>
#include <cstdint>

#define IN_F   4096
#define OUT_F  11008
#define M_TOT  512
#define BM     256
#define BN     128
#define BK     64
#define KHALF  2048
#define NCHUNK (KHALF / BK)     // 32
#define NTHREADS 384            // 8 consumer warps + 4 producer warps
#define NSTAGE 3
#define STAGE_SZ 49152          // A 32KB + B 16KB
static constexpr int SMEM_BYTES = NSTAGE * STAGE_SZ;   // 144 KB

// x converted to fp16 once per launch (scratch: __device__ global, no allocs)
__device__ __align__(16) __half g_xh[M_TOT * IN_F];

// ---------------- helpers ----------------
__device__ __forceinline__ uint32_t smem_u32(const void* p) {
    uint32_t a;
    asm("{ .reg .u64 t; cvta.to.shared.u64 t, %1; cvt.u32.u64 %0, t; }" : "=r"(a) : "l"(p));
    return a;
}

#define LDSM4(r0, r1, r2, r3, addr) \
    asm volatile("ldmatrix.sync.aligned.m8n8.x4.shared.b16 {%0,%1,%2,%3}, [%4];" \
        : "=r"(r0), "=r"(r1), "=r"(r2), "=r"(r3) : "r"(addr))

#define MMA16816(c, a, b0, b1) \
    asm volatile("mma.sync.aligned.m16n8k16.row.col.f32.f16.f16.f32 " \
        "{%0,%1,%2,%3}, {%4,%5,%6,%7}, {%8,%9}, {%0,%1,%2,%3};" \
        : "+f"((c)[0]), "+f"((c)[1]), "+f"((c)[2]), "+f"((c)[3]) \
        : "r"((a)[0]), "r"((a)[1]), "r"((a)[2]), "r"((a)[3]), "r"(b0), "r"(b1))

#define CP_ASYNC16(dst, src) \
    asm volatile("cp.async.cg.shared.global [%0], [%1], 16;" :: "r"(dst), "l"(src) : "memory")
#define CP_ASYNC_COMMIT() asm volatile("cp.async.commit_group;" ::: "memory")
#define CP_ASYNC_WAIT0()  asm volatile("cp.async.wait_group 0;" ::: "memory")

#define BAR_SYNC(id)   asm volatile("bar.sync %0, %1;"   :: "r"(id), "n"(NTHREADS) : "memory")
#define BAR_ARRIVE(id) asm volatile("bar.arrive %0, %1;" :: "r"(id), "n"(NTHREADS) : "memory")

__device__ __forceinline__ void sts128(uint32_t addr, uint4 v) {
    asm volatile("st.shared.v4.b32 [%0], {%1, %2, %3, %4};"
        :: "r"(addr), "r"(v.x), "r"(v.y), "r"(v.z), "r"(v.w) : "memory");
}

// dequant two int4-codes (stored as int32) -> packed fp16x2
__device__ __forceinline__ uint32_t packw(uint32_t q0, uint32_t q1, float s, float bz) {
    float f0 = fmaf((float)(int)q0, s, bz);
    float f1 = fmaf((float)(int)q1, s, bz);
    __half2 h = __floats2half2_rn(f0, f1);
    return *reinterpret_cast<uint32_t*>(&h);
}

// ---------------- kernel 1: x fp32 -> fp16 ----------------
__global__ void convert_x_kernel(const float* __restrict__ x) {
    int i = blockIdx.x * blockDim.x + threadIdx.x;
    float4 v = reinterpret_cast<const float4*>(x)[i];
    __half2 a = __floats2half2_rn(v.x, v.y);
    __half2 b = __floats2half2_rn(v.z, v.w);
    uint2 u;
    u.x = *reinterpret_cast<uint32_t*>(&a);
    u.y = *reinterpret_cast<uint32_t*>(&b);
    reinterpret_cast<uint2*>(g_xh)[i] = u;
}

// ---------------- kernel 2: warp-specialized dequant + HMMA GEMM ----------
// Stage layout (per stage, 48KB):
//   A: 256 rows x 64 fp16 (128B/row, SW128) at +0      (32 KB)
//   B: 128 rows x 64 fp16 (128B/row, SW128) at +32768  (16 KB)
// Producers (warps 8-11) fill stage kc%3; consumers (warps 0-7) drain.
// Named barriers: full[s] = 1+s (128 arrive + 256 sync), empty[s] = 4+s
// (256 arrive + 128 sync), count = 384.
__global__ __launch_bounds__(NTHREADS, 1)
void qlin_main_kernel(const int* __restrict__ qw,
                      const float* __restrict__ wsc,
                      const float* __restrict__ wzp,
                      const float* __restrict__ bias,
                      float* __restrict__ out) {
    extern __shared__ __align__(1024) char smem[];
    const uint32_t sb = smem_u32(smem);
    const int tid  = threadIdx.x;
    const int lane = tid & 31;
    const int wid  = tid >> 5;
    const int m0 = blockIdx.x * BM;   // 2 M-tiles
    const int n0 = blockIdx.y * BN;   // 86 N-tiles
    const int kh = blockIdx.z;        // 2 K-splits
    const int kbase = kh * KHALF;

    if (wid < 8) {
        // ================= CONSUMERS =================
        const int mwarp = wid & 3;    // 4 M-warps (64 rows each)
        const int nwarp = wid >> 2;   // 2 N-warps (64 cols each)
        const int rA = lane & 15;
        const int cA = lane >> 4;
        const int rB = (lane & 7) | (((lane >> 4) & 1) << 3);
        const int cB = (lane >> 3) & 1;
        uint32_t baseA[4], baseB[4];
        #pragma unroll
        for (int i = 0; i < 4; ++i) {
            const int row = mwarp * 64 + i * 16 + rA;
            baseA[i] = (uint32_t)(row * 128 + ((cA << 4) ^ ((row & 7) << 4)));
        }
        #pragma unroll
        for (int jj = 0; jj < 4; ++jj) {
            const int row = nwarp * 64 + jj * 16 + rB;
            baseB[jj] = (uint32_t)(32768 + row * 128 + ((cB << 4) ^ ((row & 7) << 4)));
        }

        float acc[4][8][4];
        #pragma unroll
        for (int i = 0; i < 4; ++i)
            #pragma unroll
            for (int j = 0; j < 8; ++j)
                #pragma unroll
                for (int c = 0; c < 4; ++c) acc[i][j][c] = 0.f;

        for (int kc = 0; kc < NCHUNK; ++kc) {
            const int s = kc % NSTAGE;
            BAR_SYNC(1 + s);
            const uint32_t stage = sb + (uint32_t)(s * STAGE_SZ);
            #pragma unroll
            for (int ks = 0; ks < 4; ++ks) {
                const uint32_t ax = (uint32_t)(ks << 5);
                uint32_t a[4][4];
                #pragma unroll
                for (int i = 0; i < 4; ++i)
                    LDSM4(a[i][0], a[i][1], a[i][2], a[i][3], (stage + baseA[i]) ^ ax);
                #pragma unroll
                for (int jj = 0; jj < 4; ++jj) {
                    uint32_t r0, r1, r2, r3;
                    LDSM4(r0, r1, r2, r3, (stage + baseB[jj]) ^ ax);
                    #pragma unroll
                    for (int i = 0; i < 4; ++i) {
                        MMA16816(acc[i][2 * jj], a[i], r0, r1);
                        MMA16816(acc[i][2 * jj + 1], a[i], r2, r3);
                    }
                }
            }
            BAR_ARRIVE(4 + s);
        }

        // epilogue: atomic combine (2 deterministic contributions per element)
        const int r_base = m0 + mwarp * 64 + (lane >> 2);
        #pragma unroll
        for (int j = 0; j < 8; ++j) {
            const int col = n0 + nwarp * 64 + j * 8 + (lane & 3) * 2;
            float2 bv = make_float2(0.f, 0.f);
            if (kh == 0) bv = *reinterpret_cast<const float2*>(&bias[col]);
            #pragma unroll
            for (int i = 0; i < 4; ++i) {
                const int r0 = r_base + i * 16;
                float* p0 = &out[(size_t)r0 * OUT_F + col];
                float* p1 = &out[(size_t)(r0 + 8) * OUT_F + col];
                atomicAdd(p0,     acc[i][j][0] + bv.x);
                atomicAdd(p0 + 1, acc[i][j][1] + bv.y);
                atomicAdd(p1,     acc[i][j][2] + bv.x);
                atomicAdd(p1 + 1, acc[i][j][3] + bv.y);
            }
        }
    } else {
        // ================= PRODUCERS =================
        const int ptid = tid - 256;   // 0..127
        const int rgrp = ptid >> 3;   // 0..15
        const int kp   = ptid & 7;    // 0..7

        // B codes: 8 threads/row, 8 codes (32B) each; rows t*16+rgrp, t=0..7
        const int* bsrc = qw + (size_t)(n0 + rgrp) * IN_F + kbase + kp * 8;
        float s_[8], bz_[8];
        uint4 qa[4], qb[4];           // depth-4 software pipeline

        for (int kc = 0; kc < NCHUNK; ++kc) {
            const int s = kc % NSTAGE;
            if (kc >= NSTAGE) BAR_SYNC(4 + s);
            const uint32_t stage = sb + (uint32_t)(s * STAGE_SZ);

            // refresh scales every 2 chunks (group = 128 K)
            if ((kc & 1) == 0) {
                const int g = (kbase >> 7) + (kc >> 1);
                #pragma unroll
                for (int t = 0; t < 8; ++t) {
                    const int row = n0 + t * 16 + rgrp;
                    const float sv = wsc[row * 32 + g];
                    s_[t]  = sv;
                    bz_[t] = -wzp[row * 32 + g] * sv;
                }
            }

            // A tile via cp.async: 256 rows, 16 per thread
            #pragma unroll
            for (int t = 0; t < 16; ++t) {
                const int row = t * 16 + rgrp;
                const __half* src = g_xh + (size_t)(m0 + row) * IN_F + kbase + kc * BK + kp * 8;
                const uint32_t dst = stage + (uint32_t)(row * 128)
                                   + (uint32_t)((kp << 4) ^ ((row & 7) << 4));
                CP_ASYNC16(dst, src);
            }
            CP_ASYNC_COMMIT();

            // B codes: 128 rows (t=0..7), pipelined LDG -> dequant -> STS
            #pragma unroll
            for (int t = 0; t < 4; ++t) {
                const int* p = bsrc + (size_t)(t * 16) * IN_F + kc * BK;
                qa[t] = *reinterpret_cast<const uint4*>(p);
                qb[t] = *reinterpret_cast<const uint4*>(p + 4);
            }
            #pragma unroll
            for (int t = 0; t < 8; ++t) {
                const uint4 a = qa[t & 3];
                const uint4 b = qb[t & 3];
                if (t + 4 < 8) {
                    const int* p = bsrc + (size_t)((t + 4) * 16) * IN_F + kc * BK;
                    qa[t & 3] = *reinterpret_cast<const uint4*>(p);
                    qb[t & 3] = *reinterpret_cast<const uint4*>(p + 4);
                }
                uint4 h;
                h.x = packw(a.x, a.y, s_[t], bz_[t]);
                h.y = packw(a.z, a.w, s_[t], bz_[t]);
                h.z = packw(b.x, b.y, s_[t], bz_[t]);
                h.w = packw(b.z, b.w, s_[t], bz_[t]);
                const int row = t * 16 + rgrp;
                sts128(stage + 32768u + (uint32_t)(row * 128)
                       + (uint32_t)((kp << 4) ^ ((row & 7) << 4)), h);
            }

            CP_ASYNC_WAIT0();
            BAR_ARRIVE(1 + s);
        }
    }
}

// ---------------- launch ----------------
extern "C" void kernel_launch(void* const* d_in, const int* in_sizes, int n_in,
                              void* d_out, int out_size) {
    (void)in_sizes; (void)n_in;
    const float* x    = (const float*)d_in[0];
    const int*   qw   = (const int*)d_in[1];
    const float* wsc  = (const float*)d_in[2];
    const float* wzp  = (const float*)d_in[3];
    const float* bias = (const float*)d_in[4];
    float* out = (float*)d_out;

    cudaFuncSetAttribute(qlin_main_kernel,
                         cudaFuncAttributeMaxDynamicSharedMemorySize, SMEM_BYTES);

    cudaMemsetAsync(out, 0, (size_t)out_size * sizeof(float));
    convert_x_kernel<<<2048, 256>>>(x);
    qlin_main_kernel<<<dim3(2, 86, 2), NTHREADS, SMEM_BYTES>>>(qw, wsc, wzp, bias, out);
}

// round 16
// speedup vs baseline: 2.2882x; 1.0354x over previous
#include <cuda_runtime.h>
#include <cuda_fp16.h>
#include <cstdint>

#define IN_F   4096
#define OUT_F  11008
#define M_TOT  512
#define BM     256
#define BN     128
#define BK     64
#define KHALF  2048
#define NCHUNK (KHALF / BK)     // 32
#define NTHREADS 384            // 8 consumer warps + 4 producer warps
#define NSTAGE 3
#define STAGE_SZ 49152          // A 32KB + B 16KB
static constexpr int SMEM_BYTES = NSTAGE * STAGE_SZ;   // 144 KB

// x converted to fp16 once per launch (scratch: __device__ global, no allocs)
__device__ __align__(16) __half g_xh[M_TOT * IN_F];
// kh=1 partial results (unique writer per element -> deterministic)
__device__ __align__(16) float g_p1[(size_t)M_TOT * OUT_F];

// ---------------- helpers ----------------
__device__ __forceinline__ uint32_t smem_u32(const void* p) {
    uint32_t a;
    asm("{ .reg .u64 t; cvta.to.shared.u64 t, %1; cvt.u32.u64 %0, t; }" : "=r"(a) : "l"(p));
    return a;
}

#define LDSM4(r0, r1, r2, r3, addr) \
    asm volatile("ldmatrix.sync.aligned.m8n8.x4.shared.b16 {%0,%1,%2,%3}, [%4];" \
        : "=r"(r0), "=r"(r1), "=r"(r2), "=r"(r3) : "r"(addr))

#define MMA16816(c, a, b0, b1) \
    asm volatile("mma.sync.aligned.m16n8k16.row.col.f32.f16.f16.f32 " \
        "{%0,%1,%2,%3}, {%4,%5,%6,%7}, {%8,%9}, {%0,%1,%2,%3};" \
        : "+f"((c)[0]), "+f"((c)[1]), "+f"((c)[2]), "+f"((c)[3]) \
        : "r"((a)[0]), "r"((a)[1]), "r"((a)[2]), "r"((a)[3]), "r"(b0), "r"(b1))

#define CP_ASYNC16(dst, src) \
    asm volatile("cp.async.cg.shared.global [%0], [%1], 16;" :: "r"(dst), "l"(src) : "memory")
#define CP_ASYNC_COMMIT() asm volatile("cp.async.commit_group;" ::: "memory")
#define CP_ASYNC_WAIT0()  asm volatile("cp.async.wait_group 0;" ::: "memory")

#define BAR_SYNC(id)   asm volatile("bar.sync %0, %1;"   :: "r"(id), "n"(NTHREADS) : "memory")
#define BAR_ARRIVE(id) asm volatile("bar.arrive %0, %1;" :: "r"(id), "n"(NTHREADS) : "memory")

__device__ __forceinline__ void sts128(uint32_t addr, uint4 v) {
    asm volatile("st.shared.v4.b32 [%0], {%1, %2, %3, %4};"
        :: "r"(addr), "r"(v.x), "r"(v.y), "r"(v.z), "r"(v.w) : "memory");
}

// dequant two int4-codes (stored as int32) -> packed fp16x2
__device__ __forceinline__ uint32_t packw(uint32_t q0, uint32_t q1, float s, float bz) {
    float f0 = fmaf((float)(int)q0, s, bz);
    float f1 = fmaf((float)(int)q1, s, bz);
    __half2 h = __floats2half2_rn(f0, f1);
    return *reinterpret_cast<uint32_t*>(&h);
}

// ---------------- kernel 1: x fp32 -> fp16 ----------------
__global__ void convert_x_kernel(const float* __restrict__ x) {
    int i = blockIdx.x * blockDim.x + threadIdx.x;
    float4 v = reinterpret_cast<const float4*>(x)[i];
    __half2 a = __floats2half2_rn(v.x, v.y);
    __half2 b = __floats2half2_rn(v.z, v.w);
    uint2 u;
    u.x = *reinterpret_cast<uint32_t*>(&a);
    u.y = *reinterpret_cast<uint32_t*>(&b);
    reinterpret_cast<uint2*>(g_xh)[i] = u;
}

// ---------------- kernel 3: out = out + g_p1 + bias (float4) --------------
__global__ void combine_kernel(float* __restrict__ out, const float* __restrict__ bias) {
    const size_t i = (size_t)blockIdx.x * blockDim.x + threadIdx.x;  // float4 idx
    float4 o = reinterpret_cast<float4*>(out)[i];
    const float4 p = reinterpret_cast<const float4*>(g_p1)[i];
    const float4 b = reinterpret_cast<const float4*>(bias)[i % (OUT_F / 4)];
    o.x += p.x + b.x;
    o.y += p.y + b.y;
    o.z += p.z + b.z;
    o.w += p.w + b.w;
    reinterpret_cast<float4*>(out)[i] = o;
}

// ---------------- kernel 2: warp-specialized dequant + HMMA GEMM ----------
// Stage layout (per stage, 48KB):
//   A: 256 rows x 64 fp16 (128B/row, SW128) at +0      (32 KB)
//   B: 128 rows x 64 fp16 (128B/row, SW128) at +32768  (16 KB)
// Producers (warps 8-11) fill stage kc%3; consumers (warps 0-7) drain.
// Named barriers: full[s] = 1+s, empty[s] = 4+s, count = 384.
__global__ __launch_bounds__(NTHREADS, 1)
void qlin_main_kernel(const int* __restrict__ qw,
                      const float* __restrict__ wsc,
                      const float* __restrict__ wzp,
                      float* __restrict__ out) {
    extern __shared__ __align__(1024) char smem[];
    const uint32_t sb = smem_u32(smem);
    const int tid  = threadIdx.x;
    const int lane = tid & 31;
    const int wid  = tid >> 5;
    const int m0 = blockIdx.x * BM;   // 2 M-tiles
    const int n0 = blockIdx.y * BN;   // 86 N-tiles
    const int kh = blockIdx.z;        // 2 K-splits
    const int kbase = kh * KHALF;

    if (wid < 8) {
        // ================= CONSUMERS =================
        const int mwarp = wid & 3;    // 4 M-warps (64 rows each)
        const int nwarp = wid >> 2;   // 2 N-warps (64 cols each)
        const int rA = lane & 15;
        const int cA = lane >> 4;
        const int rB = (lane & 7) | (((lane >> 4) & 1) << 3);
        const int cB = (lane >> 3) & 1;
        uint32_t baseA[4], baseB[4];
        #pragma unroll
        for (int i = 0; i < 4; ++i) {
            const int row = mwarp * 64 + i * 16 + rA;
            baseA[i] = (uint32_t)(row * 128 + ((cA << 4) ^ ((row & 7) << 4)));
        }
        #pragma unroll
        for (int jj = 0; jj < 4; ++jj) {
            const int row = nwarp * 64 + jj * 16 + rB;
            baseB[jj] = (uint32_t)(32768 + row * 128 + ((cB << 4) ^ ((row & 7) << 4)));
        }

        float acc[4][8][4];
        #pragma unroll
        for (int i = 0; i < 4; ++i)
            #pragma unroll
            for (int j = 0; j < 8; ++j)
                #pragma unroll
                for (int c = 0; c < 4; ++c) acc[i][j][c] = 0.f;

        for (int kc = 0; kc < NCHUNK; ++kc) {
            const int s = kc % NSTAGE;
            BAR_SYNC(1 + s);
            const uint32_t stage = sb + (uint32_t)(s * STAGE_SZ);
            #pragma unroll
            for (int ks = 0; ks < 4; ++ks) {
                const uint32_t ax = (uint32_t)(ks << 5);
                uint32_t a[4][4];
                #pragma unroll
                for (int i = 0; i < 4; ++i)
                    LDSM4(a[i][0], a[i][1], a[i][2], a[i][3], (stage + baseA[i]) ^ ax);
                #pragma unroll
                for (int jj = 0; jj < 4; ++jj) {
                    uint32_t r0, r1, r2, r3;
                    LDSM4(r0, r1, r2, r3, (stage + baseB[jj]) ^ ax);
                    #pragma unroll
                    for (int i = 0; i < 4; ++i) {
                        MMA16816(acc[i][2 * jj], a[i], r0, r1);
                        MMA16816(acc[i][2 * jj + 1], a[i], r2, r3);
                    }
                }
            }
            BAR_ARRIVE(4 + s);
        }

        // epilogue: plain coalesced float2 stores (unique writer per element)
        float* dst = (kh == 0) ? out : g_p1;
        const int r_base = m0 + mwarp * 64 + (lane >> 2);
        #pragma unroll
        for (int j = 0; j < 8; ++j) {
            const int col = n0 + nwarp * 64 + j * 8 + (lane & 3) * 2;
            #pragma unroll
            for (int i = 0; i < 4; ++i) {
                const int r0 = r_base + i * 16;
                *reinterpret_cast<float2*>(&dst[(size_t)r0 * OUT_F + col]) =
                    make_float2(acc[i][j][0], acc[i][j][1]);
                *reinterpret_cast<float2*>(&dst[(size_t)(r0 + 8) * OUT_F + col]) =
                    make_float2(acc[i][j][2], acc[i][j][3]);
            }
        }
    } else {
        // ================= PRODUCERS =================
        const int ptid = tid - 256;   // 0..127
        const int rgrp = ptid >> 3;   // 0..15
        const int kp   = ptid & 7;    // 0..7

        // B codes: 8 threads/row, 8 codes (32B) each; rows t*16+rgrp, t=0..7
        const int* bsrc = qw + (size_t)(n0 + rgrp) * IN_F + kbase + kp * 8;
        float s_[8], bz_[8];
        uint4 qa[4], qb[4];           // depth-4 software pipeline

        for (int kc = 0; kc < NCHUNK; ++kc) {
            const int s = kc % NSTAGE;
            if (kc >= NSTAGE) BAR_SYNC(4 + s);
            const uint32_t stage = sb + (uint32_t)(s * STAGE_SZ);

            // refresh scales every 2 chunks (group = 128 K)
            if ((kc & 1) == 0) {
                const int g = (kbase >> 7) + (kc >> 1);
                #pragma unroll
                for (int t = 0; t < 8; ++t) {
                    const int row = n0 + t * 16 + rgrp;
                    const float sv = wsc[row * 32 + g];
                    s_[t]  = sv;
                    bz_[t] = -wzp[row * 32 + g] * sv;
                }
            }

            // A tile via cp.async: 256 rows, 16 per thread
            #pragma unroll
            for (int t = 0; t < 16; ++t) {
                const int row = t * 16 + rgrp;
                const __half* src = g_xh + (size_t)(m0 + row) * IN_F + kbase + kc * BK + kp * 8;
                const uint32_t dst = stage + (uint32_t)(row * 128)
                                   + (uint32_t)((kp << 4) ^ ((row & 7) << 4));
                CP_ASYNC16(dst, src);
            }
            CP_ASYNC_COMMIT();

            // B codes: 128 rows (t=0..7), pipelined LDG -> dequant -> STS
            #pragma unroll
            for (int t = 0; t < 4; ++t) {
                const int* p = bsrc + (size_t)(t * 16) * IN_F + kc * BK;
                qa[t] = *reinterpret_cast<const uint4*>(p);
                qb[t] = *reinterpret_cast<const uint4*>(p + 4);
            }
            #pragma unroll
            for (int t = 0; t < 8; ++t) {
                const uint4 a = qa[t & 3];
                const uint4 b = qb[t & 3];
                if (t + 4 < 8) {
                    const int* p = bsrc + (size_t)((t + 4) * 16) * IN_F + kc * BK;
                    qa[t & 3] = *reinterpret_cast<const uint4*>(p);
                    qb[t & 3] = *reinterpret_cast<const uint4*>(p + 4);
                }
                uint4 h;
                h.x = packw(a.x, a.y, s_[t], bz_[t]);
                h.y = packw(a.z, a.w, s_[t], bz_[t]);
                h.z = packw(b.x, b.y, s_[t], bz_[t]);
                h.w = packw(b.z, b.w, s_[t], bz_[t]);
                const int row = t * 16 + rgrp;
                sts128(stage + 32768u + (uint32_t)(row * 128)
                       + (uint32_t)((kp << 4) ^ ((row & 7) << 4)), h);
            }

            CP_ASYNC_WAIT0();
            BAR_ARRIVE(1 + s);
        }
    }
}

// ---------------- launch ----------------
extern "C" void kernel_launch(void* const* d_in, const int* in_sizes, int n_in,
                              void* d_out, int out_size) {
    (void)in_sizes; (void)n_in; (void)out_size;
    const float* x    = (const float*)d_in[0];
    const int*   qw   = (const int*)d_in[1];
    const float* wsc  = (const float*)d_in[2];
    const float* wzp  = (const float*)d_in[3];
    const float* bias = (const float*)d_in[4];
    float* out = (float*)d_out;

    cudaFuncSetAttribute(qlin_main_kernel,
                         cudaFuncAttributeMaxDynamicSharedMemorySize, SMEM_BYTES);

    convert_x_kernel<<<2048, 256>>>(x);
    qlin_main_kernel<<<dim3(2, 86, 2), NTHREADS, SMEM_BYTES>>>(qw, wsc, wzp, out);
    // 512*11008/4 float4 elems = 1,409,024 ; /256 = 5504 blocks (exact)
    combine_kernel<<<5504, 256>>>(out, bias);
}